// round 9
// baseline (speedup 1.0000x reference)
#include <cuda_runtime.h>
#include <cuda_bf16.h>
#include <math.h>
#include <stdint.h>

#define BATCH 4
#define CCH 256
#define HWN 4096
#define NTOK 16384          // BATCH*HWN
#define CHW (CCH*HWN)
#define TOTAL (BATCH*CHW)
#define EPS_GN 1e-5f
#define LDT 40              // padded smem row length (bf16) for 32-wide K tile
#define NPART 32            // n-tiles per batch (4096/128)
#define XPAD 132            // fp32 x-tile row pad (16B aligned)

// ---------------- scratch (device globals) ------------------------------------
__device__ float g_Y[(size_t)768 * NTOK];          // [768][16384] q|k|v channel-major
__device__ float g_pos[TOTAL];                     // NCHW positional branch output
__device__ float g_Z[(size_t)CCH * NTOK];          // [256][16384] channel-major
__device__ float g_part[3][32][NPART][2];          // partial sums from GEMM epilogues
__device__ __nv_bfloat16 g_Whi[768 * 256], g_Wlo[768 * 256];
__device__ __nv_bfloat16 g_Wphi[256 * 256], g_Wplo[256 * 256];
__device__ __nv_bfloat16 g_Uhi[(size_t)NTOK * 256], g_Ulo[(size_t)NTOK * 256];

// ---------------- helpers ------------------------------------------------------
__device__ __forceinline__ uint32_t smem_u32(const void* p) {
    return (uint32_t)__cvta_generic_to_shared(p);
}
__device__ __forceinline__ unsigned short f2bf_us(float v) {
    __nv_bfloat16 b = __float2bfloat16(v);
    return *reinterpret_cast<unsigned short*>(&b);
}
__device__ __forceinline__ void cp_async16(uint32_t s, const void* g) {
    asm volatile("cp.async.cg.shared.global [%0], [%1], 16;" :: "r"(s), "l"(g));
}
__device__ __forceinline__ void cp_commit() {
    asm volatile("cp.async.commit_group;");
}
__device__ __forceinline__ void ldsm_x4(uint32_t* r, uint32_t a) {
    asm volatile("ldmatrix.sync.aligned.m8n8.x4.shared.b16 {%0,%1,%2,%3}, [%4];"
                 : "=r"(r[0]), "=r"(r[1]), "=r"(r[2]), "=r"(r[3]) : "r"(a));
}
__device__ __forceinline__ void ldsm_x2(uint32_t* r, uint32_t a) {
    asm volatile("ldmatrix.sync.aligned.m8n8.x2.shared.b16 {%0,%1}, [%2];"
                 : "=r"(r[0]), "=r"(r[1]) : "r"(a));
}
__device__ __forceinline__ void mma_bf16(float* c, const uint32_t* a, const uint32_t* b) {
    asm volatile(
        "mma.sync.aligned.m16n8k16.row.col.f32.bf16.bf16.f32 "
        "{%0,%1,%2,%3}, {%4,%5,%6,%7}, {%8,%9}, {%0,%1,%2,%3};"
        : "+f"(c[0]), "+f"(c[1]), "+f"(c[2]), "+f"(c[3])
        : "r"(a[0]), "r"(a[1]), "r"(a[2]), "r"(a[3]), "r"(b[0]), "r"(b[1]));
}
__device__ __forceinline__ uint32_t pack_bf16(float lo_el, float hi_el) {
    return ((uint32_t)f2bf_us(hi_el) << 16) | f2bf_us(lo_el);
}

// ---------------- W -> bf16 hi/lo (K-major already) ---------------------------
__global__ void convert_w_kernel(const float* __restrict__ wq, const float* __restrict__ wk,
                                 const float* __restrict__ wv, const float* __restrict__ wp) {
    int i = blockIdx.x * 256 + threadIdx.x;  // 0..262143
    float v;
    __nv_bfloat16 *hi, *lo;
    int o;
    if (i < 65536)        { v = wq[i];          o = i;          hi = g_Whi;  lo = g_Wlo; }
    else if (i < 131072)  { v = wk[i - 65536];  o = i;          hi = g_Whi;  lo = g_Wlo; }
    else if (i < 196608)  { v = wv[i - 131072]; o = i;          hi = g_Whi;  lo = g_Wlo; }
    else                  { v = wp[i - 196608]; o = i - 196608; hi = g_Wphi; lo = g_Wplo; }
    __nv_bfloat16 h = __float2bfloat16(v);
    hi[o] = h;
    lo[o] = __float2bfloat16(v - __bfloat162float(h));
}

// ---------------- GEMM1: W(bf16 split) @ x(fp32 NCHW, converted in-block) ------
// B tile built per stage: cp.async fp32 [32ch][128hw] -> smem, transpose+convert
// to token-major bf16 hi/lo tiles. 3 mma passes share tiles. Stats fused.
__global__ __launch_bounds__(256) void mma_gemm1_kernel(
    const __nv_bfloat16* __restrict__ Ahi, const __nv_bfloat16* __restrict__ Alo,
    const float* __restrict__ x, float* __restrict__ out) {
    extern __shared__ char smraw[];
    __nv_bfloat16* smA = (__nv_bfloat16*)smraw;              // [2][2][128*LDT]
    float* smX = (float*)(smraw + 40960);                    // [2][32*XPAD]
    __nv_bfloat16* smB = (__nv_bfloat16*)(smraw + 74752);    // [2][128*LDT]
    __shared__ float sred[8][4];
    const int tid = threadIdx.x;
    const int lane = tid & 31;
    const int wid = tid >> 5;
    const int wm = wid >> 2;
    const int wn = wid & 3;
    const int m0 = blockIdx.y * 128;
    const int n0 = blockIdx.x * 128;
    const int bb = n0 >> 12;
    const int hw0 = n0 & 4095;
    const float* xb = x + (size_t)bb * CHW + hw0;

    float acc[4][4][4];
#pragma unroll
    for (int i = 0; i < 4; i++)
#pragma unroll
        for (int j = 0; j < 4; j++)
#pragma unroll
            for (int r = 0; r < 4; r++) acc[i][j][r] = 0.f;

    const int lrow = tid >> 1;
    const int lch2 = (tid & 1) * 2;
    const int ctok = tid & 127;          // token for convert
    const int ckg = (tid >> 7) * 16;     // k-group 0 or 16

#define LOAD_STAGE1(buf, kc)                                                            \
    do {                                                                                \
        const int k0 = (kc) * 32;                                                       \
        {                                                                               \
            const __nv_bfloat16* ga = Ahi + (size_t)(m0 + lrow) * 256 + k0 + lch2 * 8;  \
            uint32_t d = smem_u32(smA + (buf) * 2 * 128 * LDT + lrow * LDT + lch2 * 8); \
            cp_async16(d, ga); cp_async16(d + 16, ga + 8);                              \
        }                                                                               \
        {                                                                               \
            const __nv_bfloat16* ga = Alo + (size_t)(m0 + lrow) * 256 + k0 + lch2 * 8;  \
            uint32_t d = smem_u32(smA + ((buf) * 2 + 1) * 128 * LDT + lrow * LDT + lch2 * 8); \
            cp_async16(d, ga); cp_async16(d + 16, ga + 8);                              \
        }                                                                               \
        _Pragma("unroll")                                                               \
        for (int i = 0; i < 4; i++) {                                                   \
            int idx = tid + i * 256;                                                    \
            int r = idx >> 5, c4 = idx & 31;                                            \
            cp_async16(smem_u32(smX + (buf) * 32 * XPAD + r * XPAD + c4 * 4),           \
                       xb + (size_t)(k0 + r) * HWN + c4 * 4);                           \
        }                                                                               \
        cp_commit();                                                                    \
    } while (0)

    LOAD_STAGE1(0, 0);

    int buf = 0;
    for (int kc = 0; kc < 8; kc++) {
        asm volatile("cp.async.wait_group 0;");
        __syncthreads();                         // stage data ready + prev mma done
        if (kc + 1 < 8) LOAD_STAGE1(buf ^ 1, kc + 1);

        // convert smX[buf] -> smB (token-major bf16 hi/lo)
        {
            const float* xs = smX + buf * 32 * XPAD;
            float vals[16];
#pragma unroll
            for (int i = 0; i < 16; i++) vals[i] = xs[(ckg + i) * XPAD + ctok];
            uint32_t hi[8], lo[8];
#pragma unroll
            for (int i = 0; i < 8; i++) {
                float a = vals[2 * i], c = vals[2 * i + 1];
                __nv_bfloat16 ha = __float2bfloat16(a);
                __nv_bfloat16 hc = __float2bfloat16(c);
                hi[i] = ((uint32_t)(*(unsigned short*)&hc) << 16) | (*(unsigned short*)&ha);
                lo[i] = pack_bf16(a - __bfloat162float(ha), c - __bfloat162float(hc));
            }
            uint4* dh = (uint4*)(smB + ctok * LDT + ckg);
            dh[0] = make_uint4(hi[0], hi[1], hi[2], hi[3]);
            dh[1] = make_uint4(hi[4], hi[5], hi[6], hi[7]);
            uint4* dl = (uint4*)(smB + 128 * LDT + ctok * LDT + ckg);
            dl[0] = make_uint4(lo[0], lo[1], lo[2], lo[3]);
            dl[1] = make_uint4(lo[4], lo[5], lo[6], lo[7]);
        }
        __syncthreads();

#pragma unroll
        for (int pass = 0; pass < 3; pass++) {
            const __nv_bfloat16* At = smA + buf * 2 * 128 * LDT + ((pass == 2) ? 128 * LDT : 0);
            const __nv_bfloat16* Bt = smB + ((pass == 1) ? 128 * LDT : 0);
#pragma unroll
            for (int ks = 0; ks < 2; ks++) {
                uint32_t afr[4][4];
#pragma unroll
                for (int i = 0; i < 4; i++) {
                    uint32_t a = smem_u32(&At[(wm * 64 + i * 16 + (lane & 15)) * LDT +
                                             ((lane >> 4) * 8 + ks * 16)]);
                    ldsm_x4(afr[i], a);
                }
                uint32_t bfr[4][2];
#pragma unroll
                for (int j = 0; j < 4; j++) {
                    int l2 = lane & 15;
                    uint32_t a = smem_u32(&Bt[(wn * 32 + j * 8 + (l2 & 7)) * LDT +
                                             (((l2 >> 3) & 1) * 8 + ks * 16)]);
                    ldsm_x2(bfr[j], a);
                }
#pragma unroll
                for (int i = 0; i < 4; i++)
#pragma unroll
                    for (int j = 0; j < 4; j++) mma_bf16(acc[i][j], afr[i], bfr[j]);
            }
        }
        buf ^= 1;
    }
#undef LOAD_STAGE1

    float s[2] = {0.f, 0.f}, s2[2] = {0.f, 0.f};
#pragma unroll
    for (int i = 0; i < 4; i++) {
        const int row = m0 + wm * 64 + i * 16 + (lane >> 2);
        const int gh = i >> 1;
#pragma unroll
        for (int j = 0; j < 4; j++) {
            const int col = n0 + wn * 32 + j * 8 + (lane & 3) * 2;
            float v0x = acc[i][j][0], v0y = acc[i][j][1];
            float v1x = acc[i][j][2], v1y = acc[i][j][3];
            s[gh] += (v0x + v0y) + (v1x + v1y);
            s2[gh] += v0x * v0x + v0y * v0y + v1x * v1x + v1y * v1y;
            *(float2*)(out + (size_t)row * NTOK + col) = make_float2(v0x, v0y);
            *(float2*)(out + (size_t)(row + 8) * NTOK + col) = make_float2(v1x, v1y);
        }
    }

    int slot = (blockIdx.y < 4) ? (int)(blockIdx.y >> 1) : -1;
    if (slot < 0) return;
    const int group_base = (blockIdx.y & 1) * 4;

#pragma unroll
    for (int off = 16; off > 0; off >>= 1) {
        s[0] += __shfl_xor_sync(0xffffffffu, s[0], off);
        s[1] += __shfl_xor_sync(0xffffffffu, s[1], off);
        s2[0] += __shfl_xor_sync(0xffffffffu, s2[0], off);
        s2[1] += __shfl_xor_sync(0xffffffffu, s2[1], off);
    }
    if (lane == 0) {
        sred[wid][0] = s[0]; sred[wid][1] = s[1];
        sred[wid][2] = s2[0]; sred[wid][3] = s2[1];
    }
    __syncthreads();
    if (tid < 4) {
        const int wmm = tid >> 1, gh = tid & 1;
        float ss = 0.f, ss2 = 0.f;
#pragma unroll
        for (int w = 0; w < 4; w++) {
            ss += sred[wmm * 4 + w][gh];
            ss2 += sred[wmm * 4 + w][2 + gh];
        }
        const int bxl = blockIdx.x & 31;
        const int pair = bb * 8 + group_base + wmm * 2 + gh;
        g_part[slot][pair][bxl][0] = ss;
        g_part[slot][pair][bxl][1] = ss2;
    }
}

// ---------------- GEMM2 (bf16 operands, shared-tile split) ---------------------
__global__ __launch_bounds__(256) void mma_gemm_kernel(
    const __nv_bfloat16* __restrict__ Ahi, const __nv_bfloat16* __restrict__ Alo,
    const __nv_bfloat16* __restrict__ Bhi, const __nv_bfloat16* __restrict__ Blo,
    float* __restrict__ out, const float* __restrict__ bias) {
    extern __shared__ __nv_bfloat16 smT[];   // [2 buf][4 mat][128*LDT]
    __shared__ float sred[8][4];
    const int tid = threadIdx.x;
    const int lane = tid & 31;
    const int wid = tid >> 5;
    const int wm = wid >> 2;
    const int wn = wid & 3;
    const int m0 = blockIdx.y * 128;
    const int n0 = blockIdx.x * 128;

    float acc[4][4][4];
#pragma unroll
    for (int i = 0; i < 4; i++)
#pragma unroll
        for (int j = 0; j < 4; j++)
#pragma unroll
            for (int r = 0; r < 4; r++) acc[i][j][r] = 0.f;

    const int lrow = tid >> 1;
    const int lch2 = (tid & 1) * 2;

#define TILE_BASE(buf, mat) (smT + ((buf) * 4 + (mat)) * (128 * LDT))
#define LOAD_STAGE(buf, kc)                                                             \
    do {                                                                                \
        const int k0 = (kc) * 32;                                                       \
        _Pragma("unroll")                                                               \
        for (int mat = 0; mat < 4; mat++) {                                             \
            const __nv_bfloat16* src =                                                  \
                ((mat == 0) ? Ahi : (mat == 1) ? Alo : (mat == 2) ? Bhi : Blo) +        \
                (size_t)(((mat < 2) ? m0 : n0) + lrow) * 256 + k0 + lch2 * 8;           \
            uint32_t d = smem_u32(TILE_BASE(buf, mat) + lrow * LDT + lch2 * 8);         \
            cp_async16(d, src);                                                         \
            cp_async16(d + 16, src + 8);                                                \
        }                                                                               \
        cp_commit();                                                                    \
    } while (0)

    LOAD_STAGE(0, 0);

    int buf = 0;
    for (int kc = 0; kc < 8; kc++) {
        if (kc + 1 < 8) {
            LOAD_STAGE(buf ^ 1, kc + 1);
            asm volatile("cp.async.wait_group 1;");
        } else {
            asm volatile("cp.async.wait_group 0;");
        }
        __syncthreads();

#pragma unroll
        for (int pass = 0; pass < 3; pass++) {
            const __nv_bfloat16* At = TILE_BASE(buf, (pass == 2) ? 1 : 0);
            const __nv_bfloat16* Bt = TILE_BASE(buf, (pass == 1) ? 3 : 2);
#pragma unroll
            for (int ks = 0; ks < 2; ks++) {
                uint32_t afr[4][4];
#pragma unroll
                for (int i = 0; i < 4; i++) {
                    uint32_t a = smem_u32(&At[(wm * 64 + i * 16 + (lane & 15)) * LDT +
                                             ((lane >> 4) * 8 + ks * 16)]);
                    ldsm_x4(afr[i], a);
                }
                uint32_t bfr[4][2];
#pragma unroll
                for (int j = 0; j < 4; j++) {
                    int l2 = lane & 15;
                    uint32_t a = smem_u32(&Bt[(wn * 32 + j * 8 + (l2 & 7)) * LDT +
                                             (((l2 >> 3) & 1) * 8 + ks * 16)]);
                    ldsm_x2(bfr[j], a);
                }
#pragma unroll
                for (int i = 0; i < 4; i++)
#pragma unroll
                    for (int j = 0; j < 4; j++) mma_bf16(acc[i][j], afr[i], bfr[j]);
            }
        }
        __syncthreads();
        buf ^= 1;
    }
#undef LOAD_STAGE
#undef TILE_BASE

    float s[2] = {0.f, 0.f}, s2[2] = {0.f, 0.f};
#pragma unroll
    for (int i = 0; i < 4; i++) {
        const int row = m0 + wm * 64 + i * 16 + (lane >> 2);
        const int gh = i >> 1;
        const float b0v = bias[row];
        const float b1v = bias[row + 8];
#pragma unroll
        for (int j = 0; j < 4; j++) {
            const int col = n0 + wn * 32 + j * 8 + (lane & 3) * 2;
            float v0x = acc[i][j][0] + b0v, v0y = acc[i][j][1] + b0v;
            float v1x = acc[i][j][2] + b1v, v1y = acc[i][j][3] + b1v;
            s[gh] += (v0x + v0y) + (v1x + v1y);
            s2[gh] += v0x * v0x + v0y * v0y + v1x * v1x + v1y * v1y;
            *(float2*)(out + (size_t)row * NTOK + col) = make_float2(v0x, v0y);
            *(float2*)(out + (size_t)(row + 8) * NTOK + col) = make_float2(v1x, v1y);
        }
    }

    const int group_base = blockIdx.y * 4;
#pragma unroll
    for (int off = 16; off > 0; off >>= 1) {
        s[0] += __shfl_xor_sync(0xffffffffu, s[0], off);
        s[1] += __shfl_xor_sync(0xffffffffu, s[1], off);
        s2[0] += __shfl_xor_sync(0xffffffffu, s2[0], off);
        s2[1] += __shfl_xor_sync(0xffffffffu, s2[1], off);
    }
    if (lane == 0) {
        sred[wid][0] = s[0]; sred[wid][1] = s[1];
        sred[wid][2] = s2[0]; sred[wid][3] = s2[1];
    }
    __syncthreads();
    if (tid < 4) {
        const int wmm = tid >> 1, gh = tid & 1;
        float ss = 0.f, ss2 = 0.f;
#pragma unroll
        for (int w = 0; w < 4; w++) {
            ss += sred[wmm * 4 + w][gh];
            ss2 += sred[wmm * 4 + w][2 + gh];
        }
        const int b = blockIdx.x >> 5;
        const int bxl = blockIdx.x & 31;
        const int pair = b * 8 + group_base + wmm * 2 + gh;
        g_part[2][pair][bxl][0] = ss;
        g_part[2][pair][bxl][1] = ss2;
    }
}

// ---------------- fused depthwise conv 3x3 + GeLU + conv 3x3 (padded tiles) ----
__global__ __launch_bounds__(256) void dwconv_fused_kernel(
    const float* __restrict__ x,
    const float* __restrict__ dw1, const float* __restrict__ db1,
    const float* __restrict__ dw2, const float* __restrict__ db2) {
    __shared__ float xs[66 * 68];
    __shared__ float p1[66 * 68];
    const int bc = blockIdx.x;          // b*256 + c
    const int c = bc & 255;
    const float* xb = x + (size_t)bc * HWN;
    const int tid = threadIdx.x;

    // zero both padded tiles (borders matter; interior overwritten)
#pragma unroll
    for (int i = tid; i < 66 * 68; i += 256) { xs[i] = 0.f; p1[i] = 0.f; }
    float w1[9], w2[9];
#pragma unroll
    for (int i = 0; i < 9; i++) { w1[i] = dw1[c * 9 + i]; w2[i] = dw2[c * 9 + i]; }
    const float b1 = db1[c], b2 = db2[c];
    __syncthreads();

    // load interior
#pragma unroll
    for (int i = 0; i < 4; i++) {
        int idx = tid + i * 256;          // float4 index 0..1023
        int py = idx >> 4, px4 = idx & 15;
        float4 v = *(const float4*)(xb + idx * 4);
        float* d = &xs[(py + 1) * 68 + 1 + px4 * 4];
        d[0] = v.x; d[1] = v.y; d[2] = v.z; d[3] = v.w;
    }
    __syncthreads();

#pragma unroll
    for (int i = 0; i < 16; i++) {
        int idx = tid + i * 256;
        int px = idx & 63, py = idx >> 6;
        const float* base = &xs[py * 68 + px];   // padded coords (py, px) -> top-left
        float acc = b1;
        acc = fmaf(base[0],       w1[0], acc);
        acc = fmaf(base[1],       w1[1], acc);
        acc = fmaf(base[2],       w1[2], acc);
        acc = fmaf(base[68],      w1[3], acc);
        acc = fmaf(base[69],      w1[4], acc);
        acc = fmaf(base[70],      w1[5], acc);
        acc = fmaf(base[136],     w1[6], acc);
        acc = fmaf(base[137],     w1[7], acc);
        acc = fmaf(base[138],     w1[8], acc);
        p1[(py + 1) * 68 + px + 1] = 0.5f * acc * (1.f + erff(acc * 0.70710678118654752f));
    }
    __syncthreads();

#pragma unroll
    for (int i = 0; i < 16; i++) {
        int idx = tid + i * 256;
        int px = idx & 63, py = idx >> 6;
        const float* base = &p1[py * 68 + px];
        float acc = b2;
        acc = fmaf(base[0],       w2[0], acc);
        acc = fmaf(base[1],       w2[1], acc);
        acc = fmaf(base[2],       w2[2], acc);
        acc = fmaf(base[68],      w2[3], acc);
        acc = fmaf(base[69],      w2[4], acc);
        acc = fmaf(base[70],      w2[5], acc);
        acc = fmaf(base[136],     w2[6], acc);
        acc = fmaf(base[137],     w2[7], acc);
        acc = fmaf(base[138],     w2[8], acc);
        g_pos[(size_t)bc * HWN + idx] = acc;
    }
}

// ---------------- attention via moment expansion + residual + bf16 emission ----
__global__ __launch_bounds__(1024) void attn_kernel(
    const float* __restrict__ gqg, const float* __restrict__ gqb,
    const float* __restrict__ gkg, const float* __restrict__ gkb) {
    extern __shared__ float smf[];
    __shared__ float sstat[2][8][2];  // [slot q/k][head][mean,rstd]
    float* smq = smf;                 // [256][33]
    float* smk = smf + 256 * 33;
    float* smv = smf + 2 * 256 * 33;
    float* smp = smf + 3 * 256 * 33;  // pos tile
    const int tid = threadIdx.x;
    const int warp = tid >> 5;
    const int lane = tid & 31;
    const int n0 = blockIdx.x * 32;
    const int b = n0 >> 12;
    const int hw0 = n0 & 4095;

    if (warp < 16) {
        const int sl = warp >> 3;
        const int h = warp & 7;
        float s = g_part[sl][b * 8 + h][lane][0];
        float s2 = g_part[sl][b * 8 + h][lane][1];
#pragma unroll
        for (int off = 16; off > 0; off >>= 1) {
            s += __shfl_xor_sync(0xffffffffu, s, off);
            s2 += __shfl_xor_sync(0xffffffffu, s2, off);
        }
        if (lane == 0) {
            const float inv = 1.f / 131072.f;
            float mean = s * inv;
            float var = s2 * inv - mean * mean;
            sstat[sl][h][0] = mean;
            sstat[sl][h][1] = rsqrtf(var + EPS_GN);
        }
    }

#pragma unroll
    for (int r = 0; r < 6; r++) {
        const int tens = r >> 1;
        const int slot = tid + r * 1024;
        const int row = (slot >> 3) & 255;
        const int q8 = slot & 7;
        float4 v = *(const float4*)(g_Y + (size_t)(tens * 256 + row) * NTOK + n0 + q8 * 4);
        float* dst = smf + tens * (256 * 33) + row * 33 + q8 * 4;
        dst[0] = v.x; dst[1] = v.y; dst[2] = v.z; dst[3] = v.w;
    }
#pragma unroll
    for (int r = 0; r < 2; r++) {
        const int slot = tid + r * 1024;
        const int row = (slot >> 3) & 255;
        const int q8 = slot & 7;
        float4 v = *(const float4*)(g_pos + (size_t)b * CHW + (size_t)row * HWN + hw0 + q8 * 4);
        float* dst = smp + row * 33 + q8 * 4;
        dst[0] = v.x; dst[1] = v.y; dst[2] = v.z; dst[3] = v.w;
    }
    __syncthreads();

    const float scale = 0.17677669529663687f;  // 1/sqrt(32)
    float oacc[8];
#pragma unroll 1
    for (int h = 0; h < 8; h++) {
        const int c = h * 32 + lane;
        float q = smq[c * 33 + warp];
        float k = smk[c * 33 + warp];
        float vv = smv[c * 33 + warp];
        q = (q - sstat[0][h][0]) * sstat[0][h][1] * gqg[c] + gqb[c];
        k = (k - sstat[1][h][0]) * sstat[1][h][1] * gkg[c] + gkb[c];
        float sq = q * q, sk = k * k;
#pragma unroll
        for (int off = 16; off > 0; off >>= 1) {
            sq += __shfl_xor_sync(0xffffffffu, sq, off);
            sk += __shfl_xor_sync(0xffffffffu, sk, off);
        }
        const float qn = q / fmaxf(sqrtf(sq), 1e-12f);
        const float kn = k / fmaxf(sqrtf(sk), 1e-12f);
        const float s = qn * scale;

        const float k2 = kn * kn;
        const float k3 = k2 * kn;
        const float k4 = k2 * k2;
        float a1 = kn, a2 = k2, a3 = k3, a4 = k4;
        float b0 = vv, b1m = kn * vv, b2 = k2 * vv, b3 = k3 * vv, b4 = k4 * vv;
#pragma unroll
        for (int off = 16; off > 0; off >>= 1) {
            a1 += __shfl_xor_sync(0xffffffffu, a1, off);
            a2 += __shfl_xor_sync(0xffffffffu, a2, off);
            a3 += __shfl_xor_sync(0xffffffffu, a3, off);
            a4 += __shfl_xor_sync(0xffffffffu, a4, off);
            b0 += __shfl_xor_sync(0xffffffffu, b0, off);
            b1m += __shfl_xor_sync(0xffffffffu, b1m, off);
            b2 += __shfl_xor_sync(0xffffffffu, b2, off);
            b3 += __shfl_xor_sync(0xffffffffu, b3, off);
            b4 += __shfl_xor_sync(0xffffffffu, b4, off);
        }
        const float c2 = 0.5f, c3 = 1.f / 6.f, c4 = 1.f / 24.f;
        float num = fmaf(s, fmaf(s, fmaf(s, fmaf(s, b4 * c4, b3 * c3), b2 * c2), b1m), b0);
        float den = fmaf(s, fmaf(s, fmaf(s, fmaf(s, a4 * c4, a3 * c3), a2 * c2), a1), 32.f);
        oacc[h] = __fdividef(num, den) + smp[c * 33 + warp];
    }
#pragma unroll
    for (int h = 0; h < 8; h++) smq[(h * 32 + lane) * 33 + warp] = oacc[h];
    __syncthreads();

#pragma unroll
    for (int it = 0; it < 2; it++) {
        const int j = (tid >> 6) + it * 16;   // token 0..31
        const int c0 = (tid & 63) * 4;
        float f0 = smq[(c0 + 0) * 33 + j];
        float f1 = smq[(c0 + 1) * 33 + j];
        float f2 = smq[(c0 + 2) * 33 + j];
        float f3 = smq[(c0 + 3) * 33 + j];
        ushort4 hs, ls;
        hs.x = f2bf_us(f0); hs.y = f2bf_us(f1); hs.z = f2bf_us(f2); hs.w = f2bf_us(f3);
        ls.x = f2bf_us(f0 - __bfloat162float(__float2bfloat16(f0)));
        ls.y = f2bf_us(f1 - __bfloat162float(__float2bfloat16(f1)));
        ls.z = f2bf_us(f2 - __bfloat162float(__float2bfloat16(f2)));
        ls.w = f2bf_us(f3 - __bfloat162float(__float2bfloat16(f3)));
        const size_t n = (size_t)(n0 + j);
        *(ushort4*)(g_Uhi + n * 256 + c0) = hs;
        *(ushort4*)(g_Ulo + n * 256 + c0) = ls;
    }
}

// ---------------- final GN apply (stats reduced in-block) ----------------------
__global__ void gn_apply_kernel(const float* __restrict__ gamma,
                                const float* __restrict__ beta,
                                float* __restrict__ out) {
    __shared__ float sms[2];
    const int blk0 = blockIdx.x * 256;
    const int cB = blk0 >> 12;
    const int bB = ((blk0 & 4095) * 4) >> 12;
    if (threadIdx.x < 32) {
        const int lane = threadIdx.x;
        const int pair = bB * 8 + (cB >> 5);
        float s = g_part[2][pair][lane][0];
        float s2 = g_part[2][pair][lane][1];
#pragma unroll
        for (int off = 16; off > 0; off >>= 1) {
            s += __shfl_xor_sync(0xffffffffu, s, off);
            s2 += __shfl_xor_sync(0xffffffffu, s2, off);
        }
        if (lane == 0) {
            const float inv = 1.f / 131072.f;
            float mean = s * inv;
            float var = s2 * inv - mean * mean;
            sms[0] = mean;
            sms[1] = rsqrtf(var + EPS_GN);
        }
    }
    __syncthreads();
    const int idx4 = blk0 + threadIdx.x;
    const int c = idx4 >> 12;
    const int n = (idx4 & 4095) * 4;
    const int b = n >> 12;
    const float mean = sms[0], rstd = sms[1];
    const float ga = gamma[c], be = beta[c];
    float4 v = *(const float4*)(g_Z + (size_t)idx4 * 4);
    v.x = (v.x - mean) * rstd * ga + be;
    v.y = (v.y - mean) * rstd * ga + be;
    v.z = (v.z - mean) * rstd * ga + be;
    v.w = (v.w - mean) * rstd * ga + be;
    *(float4*)(out + (size_t)b * CHW + (size_t)c * HWN + (n & 4095)) = v;
}

// ---------------- launcher -----------------------------------------------------
extern "C" void kernel_launch(void* const* d_in, const int* in_sizes, int n_in,
                              void* d_out, int out_size) {
    const float* x        = (const float*)d_in[0];
    const float* wq       = (const float*)d_in[1];
    const float* gq_gamma = (const float*)d_in[2];
    const float* gq_beta  = (const float*)d_in[3];
    const float* wk       = (const float*)d_in[4];
    const float* gk_gamma = (const float*)d_in[5];
    const float* gk_beta  = (const float*)d_in[6];
    const float* wv       = (const float*)d_in[7];
    const float* wp       = (const float*)d_in[8];
    const float* bp       = (const float*)d_in[9];
    const float* gp_gamma = (const float*)d_in[10];
    const float* gp_beta  = (const float*)d_in[11];
    const float* dw1      = (const float*)d_in[12];
    const float* db1      = (const float*)d_in[13];
    const float* dw2      = (const float*)d_in[14];
    const float* db2      = (const float*)d_in[15];
    float* out = (float*)d_out;

    const int GEMM1_SMEM = 95232;                 // A 40960 + X 33792 + B 20480
    const int GEMM2_SMEM = 2 * 4 * 128 * LDT * 2; // 81920
    static bool attr_set = false;
    if (!attr_set) {
        cudaFuncSetAttribute(attn_kernel, cudaFuncAttributeMaxDynamicSharedMemorySize, 135168);
        cudaFuncSetAttribute(mma_gemm1_kernel, cudaFuncAttributeMaxDynamicSharedMemorySize, GEMM1_SMEM);
        cudaFuncSetAttribute(mma_gemm_kernel, cudaFuncAttributeMaxDynamicSharedMemorySize, GEMM2_SMEM);
        attr_set = true;
    }

    float *g_Y_p, *g_Z_p;
    __nv_bfloat16 *whi, *wlo, *wphi, *wplo, *uhi, *ulo;
    cudaGetSymbolAddress((void**)&g_Y_p, g_Y);
    cudaGetSymbolAddress((void**)&g_Z_p, g_Z);
    cudaGetSymbolAddress((void**)&whi, g_Whi);
    cudaGetSymbolAddress((void**)&wlo, g_Wlo);
    cudaGetSymbolAddress((void**)&wphi, g_Wphi);
    cudaGetSymbolAddress((void**)&wplo, g_Wplo);
    cudaGetSymbolAddress((void**)&uhi, g_Uhi);
    cudaGetSymbolAddress((void**)&ulo, g_Ulo);

    // 1. weight conversion
    convert_w_kernel<<<1024, 256>>>(wq, wk, wv, wp);
    // 2. QKV GEMM (consumes x directly; q/k stats fused) -> g_Y [768][16384]
    mma_gemm1_kernel<<<dim3(128, 6), 256, GEMM1_SMEM>>>(whi, wlo, x, g_Y_p);
    // 3. fused positional path -> g_pos
    dwconv_fused_kernel<<<1024, 256>>>(x, dw1, db1, dw2, db2);
    // 4. attention (finalizes q/k stats in-block) + residual -> U bf16 hi/lo
    attn_kernel<<<512, 1024, 135168>>>(gq_gamma, gq_beta, gk_gamma, gk_beta);
    // 5. output projection GEMM (z stats fused) -> g_Z [256][16384]
    mma_gemm_kernel<<<dim3(128, 2), 256, GEMM2_SMEM>>>(wphi, wplo, uhi, ulo, g_Z_p, bp);
    // 6. final group norm apply (finalizes z stats in-block)
    gn_apply_kernel<<<NTOK * 256 / 1024, 256>>>(gp_gamma, gp_beta, out);
}

// round 10
// speedup vs baseline: 1.0583x; 1.0583x over previous
#include <cuda_runtime.h>
#include <cuda_bf16.h>
#include <math.h>
#include <stdint.h>

#define BATCH 4
#define CCH 256
#define HWN 4096
#define NTOK 16384          // BATCH*HWN
#define CHW (CCH*HWN)
#define TOTAL (BATCH*CHW)
#define EPS_GN 1e-5f
#define LDT 40              // padded smem row length (bf16) for 32-wide K tile
#define NPART 32            // n-tiles per batch (4096/128)
#define ATP 17              // attn smem col pad (16 tokens + 1)

// ---------------- scratch (device globals) ------------------------------------
__device__ float g_Y[(size_t)768 * NTOK];          // [768][16384] q|k|v channel-major
__device__ float g_pos[TOTAL];                     // NCHW positional branch output
__device__ float g_Z[(size_t)CCH * NTOK];          // [256][16384] channel-major
__device__ float g_part[3][32][NPART][2];          // partial sums from GEMM epilogues
__device__ __nv_bfloat16 g_Whi[768 * 256], g_Wlo[768 * 256];
__device__ __nv_bfloat16 g_Wphi[256 * 256], g_Wplo[256 * 256];
__device__ __nv_bfloat16 g_Xhi[(size_t)NTOK * 256], g_Xlo[(size_t)NTOK * 256];
__device__ __nv_bfloat16 g_Uhi[(size_t)NTOK * 256], g_Ulo[(size_t)NTOK * 256];

// ---------------- helpers ------------------------------------------------------
__device__ __forceinline__ uint32_t smem_u32(const void* p) {
    return (uint32_t)__cvta_generic_to_shared(p);
}
__device__ __forceinline__ unsigned short f2bf_us(float v) {
    __nv_bfloat16 b = __float2bfloat16(v);
    return *reinterpret_cast<unsigned short*>(&b);
}
__device__ __forceinline__ void cp_async16(uint32_t s, const void* g) {
    asm volatile("cp.async.cg.shared.global [%0], [%1], 16;" :: "r"(s), "l"(g));
}
__device__ __forceinline__ void cp_commit() {
    asm volatile("cp.async.commit_group;");
}
__device__ __forceinline__ void ldsm_x4(uint32_t* r, uint32_t a) {
    asm volatile("ldmatrix.sync.aligned.m8n8.x4.shared.b16 {%0,%1,%2,%3}, [%4];"
                 : "=r"(r[0]), "=r"(r[1]), "=r"(r[2]), "=r"(r[3]) : "r"(a));
}
__device__ __forceinline__ void ldsm_x2(uint32_t* r, uint32_t a) {
    asm volatile("ldmatrix.sync.aligned.m8n8.x2.shared.b16 {%0,%1}, [%2];"
                 : "=r"(r[0]), "=r"(r[1]) : "r"(a));
}
__device__ __forceinline__ void mma_bf16(float* c, const uint32_t* a, const uint32_t* b) {
    asm volatile(
        "mma.sync.aligned.m16n8k16.row.col.f32.bf16.bf16.f32 "
        "{%0,%1,%2,%3}, {%4,%5,%6,%7}, {%8,%9}, {%0,%1,%2,%3};"
        : "+f"(c[0]), "+f"(c[1]), "+f"(c[2]), "+f"(c[3])
        : "r"(a[0]), "r"(a[1]), "r"(a[2]), "r"(a[3]), "r"(b[0]), "r"(b[1]));
}

// ---------------- W -> bf16 hi/lo (K-major already) ---------------------------
__global__ void convert_w_kernel(const float* __restrict__ wq, const float* __restrict__ wk,
                                 const float* __restrict__ wv, const float* __restrict__ wp) {
    int i = blockIdx.x * 256 + threadIdx.x;  // 0..262143
    float v;
    __nv_bfloat16 *hi, *lo;
    int o;
    if (i < 65536)        { v = wq[i];          o = i;          hi = g_Whi;  lo = g_Wlo; }
    else if (i < 131072)  { v = wk[i - 65536];  o = i;          hi = g_Whi;  lo = g_Wlo; }
    else if (i < 196608)  { v = wv[i - 131072]; o = i;          hi = g_Whi;  lo = g_Wlo; }
    else                  { v = wp[i - 196608]; o = i - 196608; hi = g_Wphi; lo = g_Wplo; }
    __nv_bfloat16 h = __float2bfloat16(v);
    hi[o] = h;
    lo[o] = __float2bfloat16(v - __bfloat162float(h));
}

// ---------------- transpose [c][hw] fp32 -> token-major bf16 hi/lo -------------
__global__ void transpose_convert_kernel(const float* __restrict__ src, int c_stride, int b_stride,
                                         __nv_bfloat16* __restrict__ dhi,
                                         __nv_bfloat16* __restrict__ dlo) {
    __shared__ float t[32][33];
    const int hw0 = blockIdx.x * 32, c0 = blockIdx.y * 32, b = blockIdx.z;
    const int tid = threadIdx.x;
    const int rl = tid >> 3, q = tid & 7;
    float4 v = *(const float4*)(src + (size_t)b * b_stride + (size_t)(c0 + rl) * c_stride + hw0 + q * 4);
    t[rl][q * 4 + 0] = v.x; t[rl][q * 4 + 1] = v.y;
    t[rl][q * 4 + 2] = v.z; t[rl][q * 4 + 3] = v.w;
    __syncthreads();
    const int n = b * HWN + hw0 + rl;
    ushort4 hs, ls;
    float f0 = t[q * 4 + 0][rl], f1 = t[q * 4 + 1][rl];
    float f2 = t[q * 4 + 2][rl], f3 = t[q * 4 + 3][rl];
    hs.x = f2bf_us(f0); hs.y = f2bf_us(f1); hs.z = f2bf_us(f2); hs.w = f2bf_us(f3);
    ls.x = f2bf_us(f0 - __bfloat162float(__float2bfloat16(f0)));
    ls.y = f2bf_us(f1 - __bfloat162float(__float2bfloat16(f1)));
    ls.z = f2bf_us(f2 - __bfloat162float(__float2bfloat16(f2)));
    ls.w = f2bf_us(f3 - __bfloat162float(__float2bfloat16(f3)));
    *(ushort4*)(dhi + (size_t)n * 256 + c0 + q * 4) = hs;
    *(ushort4*)(dlo + (size_t)n * 256 + c0 + q * 4) = ls;
}

// ---------------- mma.sync GEMM + fused GN stats partials (R8 proven) ----------
__global__ __launch_bounds__(256) void mma_gemm_kernel(
    const __nv_bfloat16* __restrict__ Ahi, const __nv_bfloat16* __restrict__ Alo,
    const __nv_bfloat16* __restrict__ Bhi, const __nv_bfloat16* __restrict__ Blo,
    float* __restrict__ out, const float* __restrict__ bias, int gemm_id) {
    extern __shared__ __nv_bfloat16 smT[];   // [2 buf][4 mat][128*LDT]
    __shared__ float sred[8][4];
    const int tid = threadIdx.x;
    const int lane = tid & 31;
    const int wid = tid >> 5;
    const int wm = wid >> 2;
    const int wn = wid & 3;
    const int m0 = blockIdx.y * 128;
    const int n0 = blockIdx.x * 128;

    float acc[4][4][4];
#pragma unroll
    for (int i = 0; i < 4; i++)
#pragma unroll
        for (int j = 0; j < 4; j++)
#pragma unroll
            for (int r = 0; r < 4; r++) acc[i][j][r] = 0.f;

    const int lrow = tid >> 1;
    const int lch2 = (tid & 1) * 2;

#define TILE_BASE(buf, mat) (smT + ((buf) * 4 + (mat)) * (128 * LDT))
#define LOAD_STAGE(buf, kc)                                                             \
    do {                                                                                \
        const int k0 = (kc) * 32;                                                       \
        _Pragma("unroll")                                                               \
        for (int mat = 0; mat < 4; mat++) {                                             \
            const __nv_bfloat16* src =                                                  \
                ((mat == 0) ? Ahi : (mat == 1) ? Alo : (mat == 2) ? Bhi : Blo) +        \
                (size_t)(((mat < 2) ? m0 : n0) + lrow) * 256 + k0 + lch2 * 8;           \
            uint32_t d = smem_u32(TILE_BASE(buf, mat) + lrow * LDT + lch2 * 8);         \
            cp_async16(d, src);                                                         \
            cp_async16(d + 16, src + 8);                                                \
        }                                                                               \
        cp_commit();                                                                    \
    } while (0)

    LOAD_STAGE(0, 0);

    int buf = 0;
    for (int kc = 0; kc < 8; kc++) {
        if (kc + 1 < 8) {
            LOAD_STAGE(buf ^ 1, kc + 1);
            asm volatile("cp.async.wait_group 1;");
        } else {
            asm volatile("cp.async.wait_group 0;");
        }
        __syncthreads();

#pragma unroll
        for (int pass = 0; pass < 3; pass++) {
            const __nv_bfloat16* At = TILE_BASE(buf, (pass == 2) ? 1 : 0);
            const __nv_bfloat16* Bt = TILE_BASE(buf, (pass == 1) ? 3 : 2);
#pragma unroll
            for (int ks = 0; ks < 2; ks++) {
                uint32_t afr[4][4];
#pragma unroll
                for (int i = 0; i < 4; i++) {
                    uint32_t a = smem_u32(&At[(wm * 64 + i * 16 + (lane & 15)) * LDT +
                                             ((lane >> 4) * 8 + ks * 16)]);
                    ldsm_x4(afr[i], a);
                }
                uint32_t bfr[4][2];
#pragma unroll
                for (int j = 0; j < 4; j++) {
                    int l2 = lane & 15;
                    uint32_t a = smem_u32(&Bt[(wn * 32 + j * 8 + (l2 & 7)) * LDT +
                                             (((l2 >> 3) & 1) * 8 + ks * 16)]);
                    ldsm_x2(bfr[j], a);
                }
#pragma unroll
                for (int i = 0; i < 4; i++)
#pragma unroll
                    for (int j = 0; j < 4; j++) mma_bf16(acc[i][j], afr[i], bfr[j]);
            }
        }
        __syncthreads();
        buf ^= 1;
    }
#undef LOAD_STAGE
#undef TILE_BASE

    float s[2] = {0.f, 0.f}, s2[2] = {0.f, 0.f};
#pragma unroll
    for (int i = 0; i < 4; i++) {
        const int row = m0 + wm * 64 + i * 16 + (lane >> 2);
        const int gh = i >> 1;
        const float b0v = bias ? bias[row] : 0.f;
        const float b1v = bias ? bias[row + 8] : 0.f;
#pragma unroll
        for (int j = 0; j < 4; j++) {
            const int col = n0 + wn * 32 + j * 8 + (lane & 3) * 2;
            float v0x = acc[i][j][0] + b0v, v0y = acc[i][j][1] + b0v;
            float v1x = acc[i][j][2] + b1v, v1y = acc[i][j][3] + b1v;
            s[gh] += (v0x + v0y) + (v1x + v1y);
            s2[gh] += v0x * v0x + v0y * v0y + v1x * v1x + v1y * v1y;
            *(float2*)(out + (size_t)row * NTOK + col) = make_float2(v0x, v0y);
            *(float2*)(out + (size_t)(row + 8) * NTOK + col) = make_float2(v1x, v1y);
        }
    }

    int slot = (gemm_id == 0) ? ((blockIdx.y < 4) ? (int)(blockIdx.y >> 1) : -1) : 2;
    if (slot < 0) return;
    const int group_base = (gemm_id == 0) ? (blockIdx.y & 1) * 4 : blockIdx.y * 4;

#pragma unroll
    for (int off = 16; off > 0; off >>= 1) {
        s[0] += __shfl_xor_sync(0xffffffffu, s[0], off);
        s[1] += __shfl_xor_sync(0xffffffffu, s[1], off);
        s2[0] += __shfl_xor_sync(0xffffffffu, s2[0], off);
        s2[1] += __shfl_xor_sync(0xffffffffu, s2[1], off);
    }
    if (lane == 0) {
        sred[wid][0] = s[0]; sred[wid][1] = s[1];
        sred[wid][2] = s2[0]; sred[wid][3] = s2[1];
    }
    __syncthreads();
    if (tid < 4) {
        const int wmm = tid >> 1, gh = tid & 1;
        float ss = 0.f, ss2 = 0.f;
#pragma unroll
        for (int w = 0; w < 4; w++) {
            ss += sred[wmm * 4 + w][gh];
            ss2 += sred[wmm * 4 + w][2 + gh];
        }
        const int b = blockIdx.x >> 5;
        const int bxl = blockIdx.x & 31;
        const int pair = b * 8 + group_base + wmm * 2 + gh;
        g_part[slot][pair][bxl][0] = ss;
        g_part[slot][pair][bxl][1] = ss2;
    }
}

// ---------------- fused depthwise conv 3x3 + GeLU + conv 3x3 (padded tiles) ----
__global__ __launch_bounds__(256) void dwconv_fused_kernel(
    const float* __restrict__ x,
    const float* __restrict__ dw1, const float* __restrict__ db1,
    const float* __restrict__ dw2, const float* __restrict__ db2) {
    __shared__ float xs[66 * 68];
    __shared__ float p1[66 * 68];
    const int bc = blockIdx.x;          // b*256 + c
    const int c = bc & 255;
    const float* xb = x + (size_t)bc * HWN;
    const int tid = threadIdx.x;

#pragma unroll
    for (int i = tid; i < 66 * 68; i += 256) { xs[i] = 0.f; p1[i] = 0.f; }
    float w1[9], w2[9];
#pragma unroll
    for (int i = 0; i < 9; i++) { w1[i] = dw1[c * 9 + i]; w2[i] = dw2[c * 9 + i]; }
    const float b1 = db1[c], b2 = db2[c];
    __syncthreads();

#pragma unroll
    for (int i = 0; i < 4; i++) {
        int idx = tid + i * 256;
        int py = idx >> 4, px4 = idx & 15;
        float4 v = *(const float4*)(xb + idx * 4);
        float* d = &xs[(py + 1) * 68 + 1 + px4 * 4];
        d[0] = v.x; d[1] = v.y; d[2] = v.z; d[3] = v.w;
    }
    __syncthreads();

#pragma unroll
    for (int i = 0; i < 16; i++) {
        int idx = tid + i * 256;
        int px = idx & 63, py = idx >> 6;
        const float* base = &xs[py * 68 + px];
        float acc = b1;
        acc = fmaf(base[0],   w1[0], acc);
        acc = fmaf(base[1],   w1[1], acc);
        acc = fmaf(base[2],   w1[2], acc);
        acc = fmaf(base[68],  w1[3], acc);
        acc = fmaf(base[69],  w1[4], acc);
        acc = fmaf(base[70],  w1[5], acc);
        acc = fmaf(base[136], w1[6], acc);
        acc = fmaf(base[137], w1[7], acc);
        acc = fmaf(base[138], w1[8], acc);
        p1[(py + 1) * 68 + px + 1] = 0.5f * acc * (1.f + erff(acc * 0.70710678118654752f));
    }
    __syncthreads();

#pragma unroll
    for (int i = 0; i < 16; i++) {
        int idx = tid + i * 256;
        int px = idx & 63, py = idx >> 6;
        const float* base = &p1[py * 68 + px];
        float acc = b2;
        acc = fmaf(base[0],   w2[0], acc);
        acc = fmaf(base[1],   w2[1], acc);
        acc = fmaf(base[2],   w2[2], acc);
        acc = fmaf(base[68],  w2[3], acc);
        acc = fmaf(base[69],  w2[4], acc);
        acc = fmaf(base[70],  w2[5], acc);
        acc = fmaf(base[136], w2[6], acc);
        acc = fmaf(base[137], w2[7], acc);
        acc = fmaf(base[138], w2[8], acc);
        g_pos[(size_t)bc * HWN + idx] = acc;
    }
}

// ---------------- attention: 16 tokens/block, fused single butterfly -----------
// Raw-moment trick: all 10 reductions (|q|^2, k-moments m1..m4, v-moments w0..w4)
// done on UN-normalized q,k in ONE butterfly phase; normalization applied after
// via rk^m scaling ((k/|k|)^m = k^m * rk^m).
__global__ __launch_bounds__(512) void attn_kernel(
    const float* __restrict__ gqg, const float* __restrict__ gqb,
    const float* __restrict__ gkg, const float* __restrict__ gkb) {
    extern __shared__ float smf[];
    __shared__ float sstat[2][8][2];  // [slot q/k][head][mean,rstd]
    float* smq = smf;                 // [256][ATP]
    float* smk = smf + 256 * ATP;
    float* smv = smf + 2 * 256 * ATP;
    float* smp = smf + 3 * 256 * ATP; // pos tile
    const int tid = threadIdx.x;
    const int warp = tid >> 5;        // 0..15 = token
    const int lane = tid & 31;
    const int n0 = blockIdx.x * 16;
    const int b = n0 >> 12;
    const int hw0 = n0 & 4095;

    if (warp < 16) {
        const int sl = warp >> 3;
        const int h = warp & 7;
        float s = g_part[sl][b * 8 + h][lane][0];
        float s2 = g_part[sl][b * 8 + h][lane][1];
#pragma unroll
        for (int off = 16; off > 0; off >>= 1) {
            s += __shfl_xor_sync(0xffffffffu, s, off);
            s2 += __shfl_xor_sync(0xffffffffu, s2, off);
        }
        if (lane == 0) {
            const float inv = 1.f / 131072.f;
            float mean = s * inv;
            float var = s2 * inv - mean * mean;
            sstat[sl][h][0] = mean;
            sstat[sl][h][1] = rsqrtf(var + EPS_GN);
        }
    }

    // load q/k/v (channel-major) + pos (NCHW) into smem [256][ATP]
#pragma unroll
    for (int r = 0; r < 8; r++) {
        const int arr = r >> 1;                 // 0=q 1=k 2=v 3=pos
        const int idx = tid + (r & 1) * 512;    // 0..1023 float4 slots
        const int row = idx >> 2;
        const int q4 = (idx & 3) * 4;
        float4 v;
        if (arr < 3)
            v = *(const float4*)(g_Y + (size_t)(arr * 256 + row) * NTOK + n0 + q4);
        else
            v = *(const float4*)(g_pos + (size_t)b * CHW + (size_t)row * HWN + hw0 + q4);
        float* dst = smf + arr * (256 * ATP) + row * ATP + q4;
        dst[0] = v.x; dst[1] = v.y; dst[2] = v.z; dst[3] = v.w;
    }
    __syncthreads();

    const float scale = 0.17677669529663687f;  // 1/sqrt(32)
    float oacc[8];
#pragma unroll 1
    for (int h = 0; h < 8; h++) {
        const int c = h * 32 + lane;
        float q = smq[c * ATP + warp];
        float k = smk[c * ATP + warp];
        float vv = smv[c * ATP + warp];
        q = (q - sstat[0][h][0]) * sstat[0][h][1] * gqg[c] + gqb[c];
        k = (k - sstat[1][h][0]) * sstat[1][h][1] * gkg[c] + gkb[c];

        // raw moments, single fused butterfly (10-way ILP)
        const float k2 = k * k;
        const float k3 = k2 * k;
        const float k4 = k2 * k2;
        float sq = q * q;
        float m1 = k, m2 = k2, m3 = k3, m4 = k4;
        float w0 = vv, w1 = k * vv, w2 = k2 * vv, w3 = k3 * vv, w4 = k4 * vv;
#pragma unroll
        for (int off = 16; off > 0; off >>= 1) {
            sq += __shfl_xor_sync(0xffffffffu, sq, off);
            m1 += __shfl_xor_sync(0xffffffffu, m1, off);
            m2 += __shfl_xor_sync(0xffffffffu, m2, off);
            m3 += __shfl_xor_sync(0xffffffffu, m3, off);
            m4 += __shfl_xor_sync(0xffffffffu, m4, off);
            w0 += __shfl_xor_sync(0xffffffffu, w0, off);
            w1 += __shfl_xor_sync(0xffffffffu, w1, off);
            w2 += __shfl_xor_sync(0xffffffffu, w2, off);
            w3 += __shfl_xor_sync(0xffffffffu, w3, off);
            w4 += __shfl_xor_sync(0xffffffffu, w4, off);
        }
        const float rq = 1.f / fmaxf(sqrtf(sq), 1e-12f);
        const float rk = 1.f / fmaxf(sqrtf(m2), 1e-12f);
        const float rk2 = rk * rk, rk3 = rk2 * rk, rk4 = rk2 * rk2;
        const float s = q * rq * scale;

        const float c2 = 0.5f, c3 = 1.f / 6.f, c4 = 1.f / 24.f;
        const float a1 = m1 * rk, a2 = m2 * rk2, a3 = m3 * rk3, a4 = m4 * rk4;
        const float b1m = w1 * rk, b2 = w2 * rk2, b3 = w3 * rk3, b4 = w4 * rk4;
        float num = fmaf(s, fmaf(s, fmaf(s, fmaf(s, b4 * c4, b3 * c3), b2 * c2), b1m), w0);
        float den = fmaf(s, fmaf(s, fmaf(s, fmaf(s, a4 * c4, a3 * c3), a2 * c2), a1), 32.f);
        oacc[h] = __fdividef(num, den) + smp[c * ATP + warp];
    }
#pragma unroll
    for (int h = 0; h < 8; h++) smq[(h * 32 + lane) * ATP + warp] = oacc[h];
    __syncthreads();

    // emit token-major bf16 hi/lo: U[n][256]
#pragma unroll
    for (int it = 0; it < 2; it++) {
        const int idx = tid + it * 512;
        const int j = idx >> 6;            // token 0..15
        const int c0 = (idx & 63) * 4;
        float f0 = smq[(c0 + 0) * ATP + j];
        float f1 = smq[(c0 + 1) * ATP + j];
        float f2 = smq[(c0 + 2) * ATP + j];
        float f3 = smq[(c0 + 3) * ATP + j];
        ushort4 hs, ls;
        hs.x = f2bf_us(f0); hs.y = f2bf_us(f1); hs.z = f2bf_us(f2); hs.w = f2bf_us(f3);
        ls.x = f2bf_us(f0 - __bfloat162float(__float2bfloat16(f0)));
        ls.y = f2bf_us(f1 - __bfloat162float(__float2bfloat16(f1)));
        ls.z = f2bf_us(f2 - __bfloat162float(__float2bfloat16(f2)));
        ls.w = f2bf_us(f3 - __bfloat162float(__float2bfloat16(f3)));
        const size_t n = (size_t)(n0 + j);
        *(ushort4*)(g_Uhi + n * 256 + c0) = hs;
        *(ushort4*)(g_Ulo + n * 256 + c0) = ls;
    }
}

// ---------------- final GN apply (stats reduced in-block) ----------------------
__global__ void gn_apply_kernel(const float* __restrict__ gamma,
                                const float* __restrict__ beta,
                                float* __restrict__ out) {
    __shared__ float sms[2];
    const int blk0 = blockIdx.x * 256;
    const int cB = blk0 >> 12;
    const int bB = ((blk0 & 4095) * 4) >> 12;
    if (threadIdx.x < 32) {
        const int lane = threadIdx.x;
        const int pair = bB * 8 + (cB >> 5);
        float s = g_part[2][pair][lane][0];
        float s2 = g_part[2][pair][lane][1];
#pragma unroll
        for (int off = 16; off > 0; off >>= 1) {
            s += __shfl_xor_sync(0xffffffffu, s, off);
            s2 += __shfl_xor_sync(0xffffffffu, s2, off);
        }
        if (lane == 0) {
            const float inv = 1.f / 131072.f;
            float mean = s * inv;
            float var = s2 * inv - mean * mean;
            sms[0] = mean;
            sms[1] = rsqrtf(var + EPS_GN);
        }
    }
    __syncthreads();
    const int idx4 = blk0 + threadIdx.x;
    const int c = idx4 >> 12;
    const int n = (idx4 & 4095) * 4;
    const int b = n >> 12;
    const float mean = sms[0], rstd = sms[1];
    const float ga = gamma[c], be = beta[c];
    float4 v = *(const float4*)(g_Z + (size_t)idx4 * 4);
    v.x = (v.x - mean) * rstd * ga + be;
    v.y = (v.y - mean) * rstd * ga + be;
    v.z = (v.z - mean) * rstd * ga + be;
    v.w = (v.w - mean) * rstd * ga + be;
    *(float4*)(out + (size_t)b * CHW + (size_t)c * HWN + (n & 4095)) = v;
}

// ---------------- launcher -----------------------------------------------------
extern "C" void kernel_launch(void* const* d_in, const int* in_sizes, int n_in,
                              void* d_out, int out_size) {
    const float* x        = (const float*)d_in[0];
    const float* wq       = (const float*)d_in[1];
    const float* gq_gamma = (const float*)d_in[2];
    const float* gq_beta  = (const float*)d_in[3];
    const float* wk       = (const float*)d_in[4];
    const float* gk_gamma = (const float*)d_in[5];
    const float* gk_beta  = (const float*)d_in[6];
    const float* wv       = (const float*)d_in[7];
    const float* wp       = (const float*)d_in[8];
    const float* bp       = (const float*)d_in[9];
    const float* gp_gamma = (const float*)d_in[10];
    const float* gp_beta  = (const float*)d_in[11];
    const float* dw1      = (const float*)d_in[12];
    const float* db1      = (const float*)d_in[13];
    const float* dw2      = (const float*)d_in[14];
    const float* db2      = (const float*)d_in[15];
    float* out = (float*)d_out;

    const int GEMM_SMEM = 2 * 4 * 128 * LDT * 2;      // 81920
    const int ATTN_SMEM = 4 * 256 * ATP * 4;          // 69632
    static bool attr_set = false;
    if (!attr_set) {
        cudaFuncSetAttribute(attn_kernel, cudaFuncAttributeMaxDynamicSharedMemorySize, ATTN_SMEM);
        cudaFuncSetAttribute(mma_gemm_kernel, cudaFuncAttributeMaxDynamicSharedMemorySize, GEMM_SMEM);
        attr_set = true;
    }

    float *g_Y_p, *g_Z_p;
    __nv_bfloat16 *whi, *wlo, *wphi, *wplo, *xhi, *xlo, *uhi, *ulo;
    cudaGetSymbolAddress((void**)&g_Y_p, g_Y);
    cudaGetSymbolAddress((void**)&g_Z_p, g_Z);
    cudaGetSymbolAddress((void**)&whi, g_Whi);
    cudaGetSymbolAddress((void**)&wlo, g_Wlo);
    cudaGetSymbolAddress((void**)&wphi, g_Wphi);
    cudaGetSymbolAddress((void**)&wplo, g_Wplo);
    cudaGetSymbolAddress((void**)&xhi, g_Xhi);
    cudaGetSymbolAddress((void**)&xlo, g_Xlo);
    cudaGetSymbolAddress((void**)&uhi, g_Uhi);
    cudaGetSymbolAddress((void**)&ulo, g_Ulo);

    // 1. weight + input conversion
    convert_w_kernel<<<1024, 256>>>(wq, wk, wv, wp);
    transpose_convert_kernel<<<dim3(128, 8, BATCH), 256>>>(x, HWN, CHW, xhi, xlo);
    // 2. QKV GEMM (q/k stats fused) -> g_Y [768][16384]
    mma_gemm_kernel<<<dim3(128, 6), 256, GEMM_SMEM>>>(whi, wlo, xhi, xlo, g_Y_p, nullptr, 0);
    // 3. fused positional path -> g_pos
    dwconv_fused_kernel<<<1024, 256>>>(x, dw1, db1, dw2, db2);
    // 4. attention (finalizes q/k stats in-block) + residual -> U bf16 hi/lo
    attn_kernel<<<1024, 512, ATTN_SMEM>>>(gq_gamma, gq_beta, gk_gamma, gk_beta);
    // 5. output projection GEMM (z stats fused) -> g_Z [256][16384]
    mma_gemm_kernel<<<dim3(128, 2), 256, GEMM_SMEM>>>(wphi, wplo, uhi, ulo, g_Z_p, bp, 1);
    // 6. final group norm apply (finalizes z stats in-block)
    gn_apply_kernel<<<NTOK * 256 / 1024, 256>>>(gp_gamma, gp_beta, out);
}

// round 11
// speedup vs baseline: 1.3254x; 1.2524x over previous
#include <cuda_runtime.h>
#include <cuda_bf16.h>
#include <math.h>
#include <stdint.h>

#define BATCH 4
#define CCH 256
#define HWN 4096
#define NTOK 16384          // BATCH*HWN
#define CHW (CCH*HWN)
#define TOTAL (BATCH*CHW)
#define EPS_GN 1e-5f
#define LDT 40              // padded smem row length (bf16) for 32-wide K tile
#define NPART 32            // n-tiles per batch (4096/128)
#define ATP 17              // attn smem col pad (16 tokens + 1)

// ---------------- scratch (device globals) ------------------------------------
__device__ float g_Y[(size_t)768 * NTOK];          // [768][16384] q|k|v channel-major
__device__ float g_pos[TOTAL];                     // NCHW positional branch output
__device__ float g_Z[(size_t)CCH * NTOK];          // [256][16384] channel-major
__device__ float g_part[3][32][NPART][2];          // partial sums from GEMM epilogues
__device__ __nv_bfloat16 g_Whi[768 * 256], g_Wlo[768 * 256];
__device__ __nv_bfloat16 g_Wphi[256 * 256], g_Wplo[256 * 256];
__device__ __nv_bfloat16 g_Xhi[(size_t)NTOK * 256], g_Xlo[(size_t)NTOK * 256];
__device__ __nv_bfloat16 g_Uhi[(size_t)NTOK * 256], g_Ulo[(size_t)NTOK * 256];

// ---------------- helpers ------------------------------------------------------
__device__ __forceinline__ uint32_t smem_u32(const void* p) {
    return (uint32_t)__cvta_generic_to_shared(p);
}
__device__ __forceinline__ unsigned short f2bf_us(float v) {
    __nv_bfloat16 b = __float2bfloat16(v);
    return *reinterpret_cast<unsigned short*>(&b);
}
__device__ __forceinline__ void cp_async16(uint32_t s, const void* g) {
    asm volatile("cp.async.cg.shared.global [%0], [%1], 16;" :: "r"(s), "l"(g));
}
__device__ __forceinline__ void cp_commit() {
    asm volatile("cp.async.commit_group;");
}
__device__ __forceinline__ void ldsm_x4(uint32_t* r, uint32_t a) {
    asm volatile("ldmatrix.sync.aligned.m8n8.x4.shared.b16 {%0,%1,%2,%3}, [%4];"
                 : "=r"(r[0]), "=r"(r[1]), "=r"(r[2]), "=r"(r[3]) : "r"(a));
}
__device__ __forceinline__ void ldsm_x2(uint32_t* r, uint32_t a) {
    asm volatile("ldmatrix.sync.aligned.m8n8.x2.shared.b16 {%0,%1}, [%2];"
                 : "=r"(r[0]), "=r"(r[1]) : "r"(a));
}
__device__ __forceinline__ void mma_bf16(float* c, const uint32_t* a, const uint32_t* b) {
    asm volatile(
        "mma.sync.aligned.m16n8k16.row.col.f32.bf16.bf16.f32 "
        "{%0,%1,%2,%3}, {%4,%5,%6,%7}, {%8,%9}, {%0,%1,%2,%3};"
        : "+f"(c[0]), "+f"(c[1]), "+f"(c[2]), "+f"(c[3])
        : "r"(a[0]), "r"(a[1]), "r"(a[2]), "r"(a[3]), "r"(b[0]), "r"(b[1]));
}

// ---------------- W -> bf16 hi/lo (K-major already) ---------------------------
__global__ void convert_w_kernel(const float* __restrict__ wq, const float* __restrict__ wk,
                                 const float* __restrict__ wv, const float* __restrict__ wp) {
    int i = blockIdx.x * 256 + threadIdx.x;  // 0..262143
    float v;
    __nv_bfloat16 *hi, *lo;
    int o;
    if (i < 65536)        { v = wq[i];          o = i;          hi = g_Whi;  lo = g_Wlo; }
    else if (i < 131072)  { v = wk[i - 65536];  o = i;          hi = g_Whi;  lo = g_Wlo; }
    else if (i < 196608)  { v = wv[i - 131072]; o = i;          hi = g_Whi;  lo = g_Wlo; }
    else                  { v = wp[i - 196608]; o = i - 196608; hi = g_Wphi; lo = g_Wplo; }
    __nv_bfloat16 h = __float2bfloat16(v);
    hi[o] = h;
    lo[o] = __float2bfloat16(v - __bfloat162float(h));
}

// ---------------- transpose [c][hw] fp32 -> token-major bf16 hi/lo -------------
__global__ void transpose_convert_kernel(const float* __restrict__ src, int c_stride, int b_stride,
                                         __nv_bfloat16* __restrict__ dhi,
                                         __nv_bfloat16* __restrict__ dlo) {
    __shared__ float t[32][33];
    const int hw0 = blockIdx.x * 32, c0 = blockIdx.y * 32, b = blockIdx.z;
    const int tid = threadIdx.x;
    const int rl = tid >> 3, q = tid & 7;
    float4 v = *(const float4*)(src + (size_t)b * b_stride + (size_t)(c0 + rl) * c_stride + hw0 + q * 4);
    t[rl][q * 4 + 0] = v.x; t[rl][q * 4 + 1] = v.y;
    t[rl][q * 4 + 2] = v.z; t[rl][q * 4 + 3] = v.w;
    __syncthreads();
    const int n = b * HWN + hw0 + rl;
    ushort4 hs, ls;
    float f0 = t[q * 4 + 0][rl], f1 = t[q * 4 + 1][rl];
    float f2 = t[q * 4 + 2][rl], f3 = t[q * 4 + 3][rl];
    hs.x = f2bf_us(f0); hs.y = f2bf_us(f1); hs.z = f2bf_us(f2); hs.w = f2bf_us(f3);
    ls.x = f2bf_us(f0 - __bfloat162float(__float2bfloat16(f0)));
    ls.y = f2bf_us(f1 - __bfloat162float(__float2bfloat16(f1)));
    ls.z = f2bf_us(f2 - __bfloat162float(__float2bfloat16(f2)));
    ls.w = f2bf_us(f3 - __bfloat162float(__float2bfloat16(f3)));
    *(ushort4*)(dhi + (size_t)n * 256 + c0 + q * 4) = hs;
    *(ushort4*)(dlo + (size_t)n * 256 + c0 + q * 4) = ls;
}

// ---------------- mma.sync GEMM + fused GN stats partials ----------------------
// npass per block: gemm1 q,k blocks use 1 (pure bf16 hi — feeds normalized
// attention scores only), v blocks and gemm2 use the full 3-pass split.
__global__ __launch_bounds__(256) void mma_gemm_kernel(
    const __nv_bfloat16* __restrict__ Ahi, const __nv_bfloat16* __restrict__ Alo,
    const __nv_bfloat16* __restrict__ Bhi, const __nv_bfloat16* __restrict__ Blo,
    float* __restrict__ out, const float* __restrict__ bias, int gemm_id) {
    extern __shared__ __nv_bfloat16 smT[];   // [2 buf][4 mat][128*LDT]
    __shared__ float sred[8][4];
    const int tid = threadIdx.x;
    const int lane = tid & 31;
    const int wid = tid >> 5;
    const int wm = wid >> 2;
    const int wn = wid & 3;
    const int m0 = blockIdx.y * 128;
    const int n0 = blockIdx.x * 128;
    const int npass = (gemm_id == 0 && blockIdx.y < 4) ? 1 : 3;

    float acc[4][4][4];
#pragma unroll
    for (int i = 0; i < 4; i++)
#pragma unroll
        for (int j = 0; j < 4; j++)
#pragma unroll
            for (int r = 0; r < 4; r++) acc[i][j][r] = 0.f;

    const int lrow = tid >> 1;
    const int lch2 = (tid & 1) * 2;

#define TILE_BASE(buf, mat) (smT + ((buf) * 4 + (mat)) * (128 * LDT))
#define LOAD_STAGE(buf, kc)                                                             \
    do {                                                                                \
        const int k0 = (kc) * 32;                                                       \
        _Pragma("unroll")                                                               \
        for (int mat = 0; mat < 4; mat++) {                                             \
            if (npass == 1 && (mat == 1 || mat == 3)) continue;                         \
            const __nv_bfloat16* src =                                                  \
                ((mat == 0) ? Ahi : (mat == 1) ? Alo : (mat == 2) ? Bhi : Blo) +        \
                (size_t)(((mat < 2) ? m0 : n0) + lrow) * 256 + k0 + lch2 * 8;           \
            uint32_t d = smem_u32(TILE_BASE(buf, mat) + lrow * LDT + lch2 * 8);         \
            cp_async16(d, src);                                                         \
            cp_async16(d + 16, src + 8);                                                \
        }                                                                               \
        cp_commit();                                                                    \
    } while (0)

    LOAD_STAGE(0, 0);

    int buf = 0;
    for (int kc = 0; kc < 8; kc++) {
        if (kc + 1 < 8) {
            LOAD_STAGE(buf ^ 1, kc + 1);
            asm volatile("cp.async.wait_group 1;");
        } else {
            asm volatile("cp.async.wait_group 0;");
        }
        __syncthreads();

#pragma unroll 3
        for (int pass = 0; pass < npass; pass++) {
            const __nv_bfloat16* At = TILE_BASE(buf, (pass == 2) ? 1 : 0);
            const __nv_bfloat16* Bt = TILE_BASE(buf, (pass == 1) ? 3 : 2);
#pragma unroll
            for (int ks = 0; ks < 2; ks++) {
                uint32_t afr[4][4];
#pragma unroll
                for (int i = 0; i < 4; i++) {
                    uint32_t a = smem_u32(&At[(wm * 64 + i * 16 + (lane & 15)) * LDT +
                                             ((lane >> 4) * 8 + ks * 16)]);
                    ldsm_x4(afr[i], a);
                }
                uint32_t bfr[4][2];
#pragma unroll
                for (int j = 0; j < 4; j++) {
                    int l2 = lane & 15;
                    uint32_t a = smem_u32(&Bt[(wn * 32 + j * 8 + (l2 & 7)) * LDT +
                                             (((l2 >> 3) & 1) * 8 + ks * 16)]);
                    ldsm_x2(bfr[j], a);
                }
#pragma unroll
                for (int i = 0; i < 4; i++)
#pragma unroll
                    for (int j = 0; j < 4; j++) mma_bf16(acc[i][j], afr[i], bfr[j]);
            }
        }
        __syncthreads();
        buf ^= 1;
    }
#undef LOAD_STAGE
#undef TILE_BASE

    float s[2] = {0.f, 0.f}, s2[2] = {0.f, 0.f};
#pragma unroll
    for (int i = 0; i < 4; i++) {
        const int row = m0 + wm * 64 + i * 16 + (lane >> 2);
        const int gh = i >> 1;
        const float b0v = bias ? bias[row] : 0.f;
        const float b1v = bias ? bias[row + 8] : 0.f;
#pragma unroll
        for (int j = 0; j < 4; j++) {
            const int col = n0 + wn * 32 + j * 8 + (lane & 3) * 2;
            float v0x = acc[i][j][0] + b0v, v0y = acc[i][j][1] + b0v;
            float v1x = acc[i][j][2] + b1v, v1y = acc[i][j][3] + b1v;
            s[gh] += (v0x + v0y) + (v1x + v1y);
            s2[gh] += v0x * v0x + v0y * v0y + v1x * v1x + v1y * v1y;
            *(float2*)(out + (size_t)row * NTOK + col) = make_float2(v0x, v0y);
            *(float2*)(out + (size_t)(row + 8) * NTOK + col) = make_float2(v1x, v1y);
        }
    }

    int slot = (gemm_id == 0) ? ((blockIdx.y < 4) ? (int)(blockIdx.y >> 1) : -1) : 2;
    if (slot < 0) return;
    const int group_base = (gemm_id == 0) ? (blockIdx.y & 1) * 4 : blockIdx.y * 4;

#pragma unroll
    for (int off = 16; off > 0; off >>= 1) {
        s[0] += __shfl_xor_sync(0xffffffffu, s[0], off);
        s[1] += __shfl_xor_sync(0xffffffffu, s[1], off);
        s2[0] += __shfl_xor_sync(0xffffffffu, s2[0], off);
        s2[1] += __shfl_xor_sync(0xffffffffu, s2[1], off);
    }
    if (lane == 0) {
        sred[wid][0] = s[0]; sred[wid][1] = s[1];
        sred[wid][2] = s2[0]; sred[wid][3] = s2[1];
    }
    __syncthreads();
    if (tid < 4) {
        const int wmm = tid >> 1, gh = tid & 1;
        float ss = 0.f, ss2 = 0.f;
#pragma unroll
        for (int w = 0; w < 4; w++) {
            ss += sred[wmm * 4 + w][gh];
            ss2 += sred[wmm * 4 + w][2 + gh];
        }
        const int b = blockIdx.x >> 5;
        const int bxl = blockIdx.x & 31;
        const int pair = b * 8 + group_base + wmm * 2 + gh;
        g_part[slot][pair][bxl][0] = ss;
        g_part[slot][pair][bxl][1] = ss2;
    }
}

// ---------------- fused depthwise conv 3x3 + GeLU + conv 3x3 -------------------
// 4 horizontal pixels per thread-iteration: 6 wide LDS feed 36 FMA.
__global__ __launch_bounds__(256) void dwconv_fused_kernel(
    const float* __restrict__ x,
    const float* __restrict__ dw1, const float* __restrict__ db1,
    const float* __restrict__ dw2, const float* __restrict__ db2) {
    __shared__ float xs[66 * 68];
    __shared__ float p1[66 * 68];
    const int bc = blockIdx.x;          // b*256 + c
    const int c = bc & 255;
    const float* xb = x + (size_t)bc * HWN;
    const int tid = threadIdx.x;

#pragma unroll
    for (int i = tid; i < 66 * 68; i += 256) { xs[i] = 0.f; p1[i] = 0.f; }
    float w1[9], w2[9];
#pragma unroll
    for (int i = 0; i < 9; i++) { w1[i] = dw1[c * 9 + i]; w2[i] = dw2[c * 9 + i]; }
    const float b1 = db1[c], b2 = db2[c];
    __syncthreads();

#pragma unroll
    for (int i = 0; i < 4; i++) {
        int idx = tid + i * 256;
        int py = idx >> 4, px4 = idx & 15;
        float4 v = *(const float4*)(xb + idx * 4);
        float* d = &xs[(py + 1) * 68 + 1 + px4 * 4];
        d[0] = v.x; d[1] = v.y; d[2] = v.z; d[3] = v.w;
    }
    __syncthreads();

#pragma unroll
    for (int i = 0; i < 4; i++) {
        int idx = tid + i * 256;              // pixel-group id
        int px4 = (idx & 15) * 4, py = idx >> 4;
        const float* base = &xs[py * 68 + px4];
        float r0[6], r1[6], r2[6];
        *(float4*)&r0[0] = *(const float4*)(base);
        *(float2*)&r0[4] = *(const float2*)(base + 4);
        *(float4*)&r1[0] = *(const float4*)(base + 68);
        *(float2*)&r1[4] = *(const float2*)(base + 72);
        *(float4*)&r2[0] = *(const float4*)(base + 136);
        *(float2*)&r2[4] = *(const float2*)(base + 140);
        float* prow = &p1[(py + 1) * 68 + px4 + 1];
#pragma unroll
        for (int p = 0; p < 4; p++) {
            float acc = b1;
            acc = fmaf(r0[p],     w1[0], acc);
            acc = fmaf(r0[p + 1], w1[1], acc);
            acc = fmaf(r0[p + 2], w1[2], acc);
            acc = fmaf(r1[p],     w1[3], acc);
            acc = fmaf(r1[p + 1], w1[4], acc);
            acc = fmaf(r1[p + 2], w1[5], acc);
            acc = fmaf(r2[p],     w1[6], acc);
            acc = fmaf(r2[p + 1], w1[7], acc);
            acc = fmaf(r2[p + 2], w1[8], acc);
            prow[p] = 0.5f * acc * (1.f + erff(acc * 0.70710678118654752f));
        }
    }
    __syncthreads();

#pragma unroll
    for (int i = 0; i < 4; i++) {
        int idx = tid + i * 256;
        int px4 = (idx & 15) * 4, py = idx >> 4;
        const float* base = &p1[py * 68 + px4];
        float r0[6], r1[6], r2[6];
        *(float4*)&r0[0] = *(const float4*)(base);
        *(float2*)&r0[4] = *(const float2*)(base + 4);
        *(float4*)&r1[0] = *(const float4*)(base + 68);
        *(float2*)&r1[4] = *(const float2*)(base + 72);
        *(float4*)&r2[0] = *(const float4*)(base + 136);
        *(float2*)&r2[4] = *(const float2*)(base + 140);
        float4 ov;
        float* po = &ov.x;
#pragma unroll
        for (int p = 0; p < 4; p++) {
            float acc = b2;
            acc = fmaf(r0[p],     w2[0], acc);
            acc = fmaf(r0[p + 1], w2[1], acc);
            acc = fmaf(r0[p + 2], w2[2], acc);
            acc = fmaf(r1[p],     w2[3], acc);
            acc = fmaf(r1[p + 1], w2[4], acc);
            acc = fmaf(r1[p + 2], w2[5], acc);
            acc = fmaf(r2[p],     w2[6], acc);
            acc = fmaf(r2[p + 1], w2[7], acc);
            acc = fmaf(r2[p + 2], w2[8], acc);
            po[p] = acc;
        }
        *(float4*)(g_pos + (size_t)bc * HWN + py * 64 + px4) = ov;
    }
}

// ---------------- attention: 16 tokens/block, fused single butterfly -----------
__global__ __launch_bounds__(512) void attn_kernel(
    const float* __restrict__ gqg, const float* __restrict__ gqb,
    const float* __restrict__ gkg, const float* __restrict__ gkb) {
    extern __shared__ float smf[];
    __shared__ float sstat[2][8][2];  // [slot q/k][head][mean,rstd]
    float* smq = smf;                 // [256][ATP]
    float* smk = smf + 256 * ATP;
    float* smv = smf + 2 * 256 * ATP;
    float* smp = smf + 3 * 256 * ATP; // pos tile
    const int tid = threadIdx.x;
    const int warp = tid >> 5;        // 0..15 = token
    const int lane = tid & 31;
    const int n0 = blockIdx.x * 16;
    const int b = n0 >> 12;
    const int hw0 = n0 & 4095;

    if (warp < 16) {
        const int sl = warp >> 3;
        const int h = warp & 7;
        float s = g_part[sl][b * 8 + h][lane][0];
        float s2 = g_part[sl][b * 8 + h][lane][1];
#pragma unroll
        for (int off = 16; off > 0; off >>= 1) {
            s += __shfl_xor_sync(0xffffffffu, s, off);
            s2 += __shfl_xor_sync(0xffffffffu, s2, off);
        }
        if (lane == 0) {
            const float inv = 1.f / 131072.f;
            float mean = s * inv;
            float var = s2 * inv - mean * mean;
            sstat[sl][h][0] = mean;
            sstat[sl][h][1] = rsqrtf(var + EPS_GN);
        }
    }

#pragma unroll
    for (int r = 0; r < 8; r++) {
        const int arr = r >> 1;                 // 0=q 1=k 2=v 3=pos
        const int idx = tid + (r & 1) * 512;
        const int row = idx >> 2;
        const int q4 = (idx & 3) * 4;
        float4 v;
        if (arr < 3)
            v = *(const float4*)(g_Y + (size_t)(arr * 256 + row) * NTOK + n0 + q4);
        else
            v = *(const float4*)(g_pos + (size_t)b * CHW + (size_t)row * HWN + hw0 + q4);
        float* dst = smf + arr * (256 * ATP) + row * ATP + q4;
        dst[0] = v.x; dst[1] = v.y; dst[2] = v.z; dst[3] = v.w;
    }
    __syncthreads();

    const float scale = 0.17677669529663687f;  // 1/sqrt(32)
    float oacc[8];
#pragma unroll 1
    for (int h = 0; h < 8; h++) {
        const int c = h * 32 + lane;
        float q = smq[c * ATP + warp];
        float k = smk[c * ATP + warp];
        float vv = smv[c * ATP + warp];
        q = (q - sstat[0][h][0]) * sstat[0][h][1] * gqg[c] + gqb[c];
        k = (k - sstat[1][h][0]) * sstat[1][h][1] * gkg[c] + gkb[c];

        const float k2 = k * k;
        const float k3 = k2 * k;
        const float k4 = k2 * k2;
        float sq = q * q;
        float m1 = k, m2 = k2, m3 = k3, m4 = k4;
        float w0 = vv, w1 = k * vv, w2 = k2 * vv, w3 = k3 * vv, w4 = k4 * vv;
#pragma unroll
        for (int off = 16; off > 0; off >>= 1) {
            sq += __shfl_xor_sync(0xffffffffu, sq, off);
            m1 += __shfl_xor_sync(0xffffffffu, m1, off);
            m2 += __shfl_xor_sync(0xffffffffu, m2, off);
            m3 += __shfl_xor_sync(0xffffffffu, m3, off);
            m4 += __shfl_xor_sync(0xffffffffu, m4, off);
            w0 += __shfl_xor_sync(0xffffffffu, w0, off);
            w1 += __shfl_xor_sync(0xffffffffu, w1, off);
            w2 += __shfl_xor_sync(0xffffffffu, w2, off);
            w3 += __shfl_xor_sync(0xffffffffu, w3, off);
            w4 += __shfl_xor_sync(0xffffffffu, w4, off);
        }
        const float rq = 1.f / fmaxf(sqrtf(sq), 1e-12f);
        const float rk = 1.f / fmaxf(sqrtf(m2), 1e-12f);
        const float rk2 = rk * rk, rk3 = rk2 * rk, rk4 = rk2 * rk2;
        const float s = q * rq * scale;

        const float c2 = 0.5f, c3 = 1.f / 6.f, c4 = 1.f / 24.f;
        const float a1 = m1 * rk, a2 = m2 * rk2, a3 = m3 * rk3, a4 = m4 * rk4;
        const float b1m = w1 * rk, b2 = w2 * rk2, b3 = w3 * rk3, b4 = w4 * rk4;
        float num = fmaf(s, fmaf(s, fmaf(s, fmaf(s, b4 * c4, b3 * c3), b2 * c2), b1m), w0);
        float den = fmaf(s, fmaf(s, fmaf(s, fmaf(s, a4 * c4, a3 * c3), a2 * c2), a1), 32.f);
        oacc[h] = __fdividef(num, den) + smp[c * ATP + warp];
    }
#pragma unroll
    for (int h = 0; h < 8; h++) smq[(h * 32 + lane) * ATP + warp] = oacc[h];
    __syncthreads();

#pragma unroll
    for (int it = 0; it < 2; it++) {
        const int idx = tid + it * 512;
        const int j = idx >> 6;            // token 0..15
        const int c0 = (idx & 63) * 4;
        float f0 = smq[(c0 + 0) * ATP + j];
        float f1 = smq[(c0 + 1) * ATP + j];
        float f2 = smq[(c0 + 2) * ATP + j];
        float f3 = smq[(c0 + 3) * ATP + j];
        ushort4 hs, ls;
        hs.x = f2bf_us(f0); hs.y = f2bf_us(f1); hs.z = f2bf_us(f2); hs.w = f2bf_us(f3);
        ls.x = f2bf_us(f0 - __bfloat162float(__float2bfloat16(f0)));
        ls.y = f2bf_us(f1 - __bfloat162float(__float2bfloat16(f1)));
        ls.z = f2bf_us(f2 - __bfloat162float(__float2bfloat16(f2)));
        ls.w = f2bf_us(f3 - __bfloat162float(__float2bfloat16(f3)));
        const size_t n = (size_t)(n0 + j);
        *(ushort4*)(g_Uhi + n * 256 + c0) = hs;
        *(ushort4*)(g_Ulo + n * 256 + c0) = ls;
    }
}

// ---------------- final GN apply (stats reduced in-block) ----------------------
__global__ void gn_apply_kernel(const float* __restrict__ gamma,
                                const float* __restrict__ beta,
                                float* __restrict__ out) {
    __shared__ float sms[2];
    const int blk0 = blockIdx.x * 256;
    const int cB = blk0 >> 12;
    const int bB = ((blk0 & 4095) * 4) >> 12;
    if (threadIdx.x < 32) {
        const int lane = threadIdx.x;
        const int pair = bB * 8 + (cB >> 5);
        float s = g_part[2][pair][lane][0];
        float s2 = g_part[2][pair][lane][1];
#pragma unroll
        for (int off = 16; off > 0; off >>= 1) {
            s += __shfl_xor_sync(0xffffffffu, s, off);
            s2 += __shfl_xor_sync(0xffffffffu, s2, off);
        }
        if (lane == 0) {
            const float inv = 1.f / 131072.f;
            float mean = s * inv;
            float var = s2 * inv - mean * mean;
            sms[0] = mean;
            sms[1] = rsqrtf(var + EPS_GN);
        }
    }
    __syncthreads();
    const int idx4 = blk0 + threadIdx.x;
    const int c = idx4 >> 12;
    const int n = (idx4 & 4095) * 4;
    const int b = n >> 12;
    const float mean = sms[0], rstd = sms[1];
    const float ga = gamma[c], be = beta[c];
    float4 v = *(const float4*)(g_Z + (size_t)idx4 * 4);
    v.x = (v.x - mean) * rstd * ga + be;
    v.y = (v.y - mean) * rstd * ga + be;
    v.z = (v.z - mean) * rstd * ga + be;
    v.w = (v.w - mean) * rstd * ga + be;
    *(float4*)(out + (size_t)b * CHW + (size_t)c * HWN + (n & 4095)) = v;
}

// ---------------- launcher -----------------------------------------------------
extern "C" void kernel_launch(void* const* d_in, const int* in_sizes, int n_in,
                              void* d_out, int out_size) {
    const float* x        = (const float*)d_in[0];
    const float* wq       = (const float*)d_in[1];
    const float* gq_gamma = (const float*)d_in[2];
    const float* gq_beta  = (const float*)d_in[3];
    const float* wk       = (const float*)d_in[4];
    const float* gk_gamma = (const float*)d_in[5];
    const float* gk_beta  = (const float*)d_in[6];
    const float* wv       = (const float*)d_in[7];
    const float* wp       = (const float*)d_in[8];
    const float* bp       = (const float*)d_in[9];
    const float* gp_gamma = (const float*)d_in[10];
    const float* gp_beta  = (const float*)d_in[11];
    const float* dw1      = (const float*)d_in[12];
    const float* db1      = (const float*)d_in[13];
    const float* dw2      = (const float*)d_in[14];
    const float* db2      = (const float*)d_in[15];
    float* out = (float*)d_out;

    const int GEMM_SMEM = 2 * 4 * 128 * LDT * 2;      // 81920
    const int ATTN_SMEM = 4 * 256 * ATP * 4;          // 69632
    static bool attr_set = false;
    if (!attr_set) {
        cudaFuncSetAttribute(attn_kernel, cudaFuncAttributeMaxDynamicSharedMemorySize, ATTN_SMEM);
        cudaFuncSetAttribute(mma_gemm_kernel, cudaFuncAttributeMaxDynamicSharedMemorySize, GEMM_SMEM);
        attr_set = true;
    }

    float *g_Y_p, *g_Z_p;
    __nv_bfloat16 *whi, *wlo, *wphi, *wplo, *xhi, *xlo, *uhi, *ulo;
    cudaGetSymbolAddress((void**)&g_Y_p, g_Y);
    cudaGetSymbolAddress((void**)&g_Z_p, g_Z);
    cudaGetSymbolAddress((void**)&whi, g_Whi);
    cudaGetSymbolAddress((void**)&wlo, g_Wlo);
    cudaGetSymbolAddress((void**)&wphi, g_Wphi);
    cudaGetSymbolAddress((void**)&wplo, g_Wplo);
    cudaGetSymbolAddress((void**)&xhi, g_Xhi);
    cudaGetSymbolAddress((void**)&xlo, g_Xlo);
    cudaGetSymbolAddress((void**)&uhi, g_Uhi);
    cudaGetSymbolAddress((void**)&ulo, g_Ulo);

    // 1. weight + input conversion
    convert_w_kernel<<<1024, 256>>>(wq, wk, wv, wp);
    transpose_convert_kernel<<<dim3(128, 8, BATCH), 256>>>(x, HWN, CHW, xhi, xlo);
    // 2. QKV GEMM (q,k single-pass bf16; v 3-pass; q/k stats fused)
    mma_gemm_kernel<<<dim3(128, 6), 256, GEMM_SMEM>>>(whi, wlo, xhi, xlo, g_Y_p, nullptr, 0);
    // 3. fused positional path -> g_pos
    dwconv_fused_kernel<<<1024, 256>>>(x, dw1, db1, dw2, db2);
    // 4. attention (finalizes q/k stats in-block) + residual -> U bf16 hi/lo
    attn_kernel<<<1024, 512, ATTN_SMEM>>>(gq_gamma, gq_beta, gk_gamma, gk_beta);
    // 5. output projection GEMM (3-pass; z stats fused) -> g_Z [256][16384]
    mma_gemm_kernel<<<dim3(128, 2), 256, GEMM_SMEM>>>(wphi, wplo, uhi, ulo, g_Z_p, bp, 1);
    // 6. final group norm apply (finalizes z stats in-block)
    gn_apply_kernel<<<NTOK * 256 / 1024, 256>>>(gp_gamma, gp_beta, out);
}